// round 10
// baseline (speedup 1.0000x reference)
#include <cuda_runtime.h>
#include <cstdint>

// Problem constants
constexpr int B_   = 8;
constexpr int H_   = 8;
constexpr int LQ_  = 1024;
constexpr int LM_  = 4096;
constexpr int DM_  = 512;
constexpr int DK_  = 64;
constexpr int TOPK_ = 32;

// Attention kernel tiling
constexpr int QT   = 32;    // queries per block (4 rows per warp)
constexpr int CK   = 128;   // key chunk cached in smem (32 KB)

// Scratch (static device arrays: allocation-free)
__device__ float g_q[B_*H_*LQ_*DK_];   // 16 MB  [B,H,LQ,Dk]
__device__ float g_k[B_*H_*LM_*DK_];   // 64 MB  [B,H,LM,Dk]
__device__ float g_v[B_*H_*LM_*DK_];   // 64 MB  [B,H,LM,Dk]
__device__ float g_x[B_*LQ_*DM_];      // 16 MB  [B,LQ,DM] pre-output-proj

// ---------------- attention smem layout (floats) ---------------------------
constexpr int OFF_QS  = 0;                 // 2048 : Q tile 32x64
constexpr int OFF_KS  = OFF_QS + QT*DK_;   // 8192 : K chunk 128x64, xor-swizzled float4
constexpr int OFF_SCC = OFF_KS + CK*DK_;   // 4096 : score staging 32x128 (ordu uints)
constexpr int SMEM_FLOATS = OFF_SCC + QT*CK;
constexpr int SMEM_BYTES  = SMEM_FLOATS * 4;   // 57344 B -> 3 blocks/SM

// order-preserving float -> uint, and inverse
__device__ __forceinline__ unsigned ordu(float x) {
    unsigned u = __float_as_uint(x);
    return (u & 0x80000000u) ? ~u : (u | 0x80000000u);
}
__device__ __forceinline__ float iordu(unsigned v) {
    unsigned u = (v & 0x80000000u) ? (v ^ 0x80000000u) : ~v;
    return __uint_as_float(u);
}

// ---------------- packed f32x2 primitives (lanewise IEEE fp32) -------------
typedef unsigned long long ull;

__device__ __forceinline__ ull pack2(float lo, float hi) {
    ull d; asm("mov.b64 %0, {%1, %2};" : "=l"(d) : "f"(lo), "f"(hi)); return d;
}
__device__ __forceinline__ void unpack2(ull v, float& lo, float& hi) {
    asm("mov.b64 {%0, %1}, %2;" : "=f"(lo), "=f"(hi) : "l"(v));
}
__device__ __forceinline__ ull fma2(ull a, ull b, ull c) {
    ull d; asm("fma.rn.f32x2 %0, %1, %2, %3;" : "=l"(d) : "l"(a), "l"(b), "l"(c)); return d;
}
__device__ __forceinline__ ull mul2(ull a, ull b) {
    ull d; asm("mul.rn.f32x2 %0, %1, %2;" : "=l"(d) : "l"(a), "l"(b)); return d;
}
__device__ __forceinline__ ull add2(ull a, ull b) {
    ull d; asm("add.rn.f32x2 %0, %1, %2;" : "=l"(d) : "l"(a), "l"(b)); return d;
}

// ---------------------------------------------------------------------------
// SGEMM body: C = A[M,512] @ W[512,512]^T + bias (torch Linear).
// Tile 128m x 64n, 256 threads, 8x4 outputs/thread => ~110 regs => 2 blocks/SM
// so sync convoys of the two resident blocks interleave.
// Per-output arithmetic (values and order) IDENTICAL to rounds 2-9:
// two-level fold, k ascending, ull packs adjacent even n (independent lanes).
// A duplicated in smem ((a,a) broadcast pairs); B plain, LDS.128 per thread.
// ---------------------------------------------------------------------------
__device__ __forceinline__ void gemm_body(
    const float* __restrict__ A, const float* __restrict__ W,
    const float* __restrict__ bias, float* __restrict__ C,
    int L, int head_major, int m0, int n0)
{
    __shared__ __align__(16) float AsD[2][8][256];   // duplicated A (m=128): 16 KB
    __shared__ __align__(16) float Bs [2][8][64];    // plain B (n=64): 4 KB

    const int t  = threadIdx.x;
    const int tx = t & 15;          // n-group: 4 n = 2 ull (16B aligned)
    const int ty = t >> 4;          // m-group: 8 m rows (0..15)
    const int lr = t >> 1;          // A staging row 0..127
    const int lc = (t & 1) << 2;    // k sub-offset 0 or 4

    const bool doB = (t < 128);
    const int lrB  = t >> 1;        // B staging row 0..63 (when doB)

    const float* Ap = A + (size_t)(m0 + lr) * DM_ + lc;
    const float* Wp = W + (size_t)(n0 + (doB ? lrB : 0)) * DM_ + lc;

    // stage k-tile 0 into buffer 0
    {
        float4 av = *(const float4*)Ap;
        ((ull*)AsD[0][lc+0])[lr] = pack2(av.x, av.x);
        ((ull*)AsD[0][lc+1])[lr] = pack2(av.y, av.y);
        ((ull*)AsD[0][lc+2])[lr] = pack2(av.z, av.z);
        ((ull*)AsD[0][lc+3])[lr] = pack2(av.w, av.w);
        if (doB) {
            float4 wv = *(const float4*)Wp;
            Bs[0][lc+0][lrB] = wv.x;
            Bs[0][lc+1][lrB] = wv.y;
            Bs[0][lc+2][lrB] = wv.z;
            Bs[0][lc+3][lrB] = wv.w;
        }
    }
    __syncthreads();

    ull acc2[8][2];
    #pragma unroll
    for (int i = 0; i < 8; i++) {
        acc2[i][0] = pack2(0.f, 0.f);
        acc2[i][1] = pack2(0.f, 0.f);
    }

    #pragma unroll 1
    for (int k0 = 0; k0 < DM_; k0 += 8) {
        const int  p    = (k0 >> 3) & 1;
        const bool more = (k0 + 8) < DM_;
        float4 av, wv;
        if (more) {
            av = *(const float4*)(Ap + k0 + 8);
            if (doB) wv = *(const float4*)(Wp + k0 + 8);
        }

        ull cacc2[8][2];
        #pragma unroll
        for (int k = 0; k < 8; k++) {
            // a (duplicated): 8 ull = 4x LDS.128, 2 distinct addrs per warp
            ull a2[8];
            {
                const ulonglong2* ar = (const ulonglong2*)&AsD[p][k][0];
                #pragma unroll
                for (int ii = 0; ii < 4; ii++) {
                    ulonglong2 v = ar[ty*4 + ii];
                    a2[2*ii]   = v.x;
                    a2[2*ii+1] = v.y;
                }
            }
            // b: 4 consecutive n = 2 ull via one conflict-free LDS.128
            ull b2[2];
            {
                ulonglong2 v = *(const ulonglong2*)&Bs[p][k][tx*4];
                b2[0] = v.x; b2[1] = v.y;
            }
            if (k == 0) {
                #pragma unroll
                for (int i = 0; i < 8; i++) {
                    cacc2[i][0] = mul2(a2[i], b2[0]);
                    cacc2[i][1] = mul2(a2[i], b2[1]);
                }
            } else {
                #pragma unroll
                for (int i = 0; i < 8; i++) {
                    cacc2[i][0] = fma2(a2[i], b2[0], cacc2[i][0]);
                    cacc2[i][1] = fma2(a2[i], b2[1], cacc2[i][1]);
                }
            }
        }
        #pragma unroll
        for (int i = 0; i < 8; i++) {
            acc2[i][0] = add2(acc2[i][0], cacc2[i][0]);
            acc2[i][1] = add2(acc2[i][1], cacc2[i][1]);
        }

        if (more) {
            const int q = p ^ 1;
            ((ull*)AsD[q][lc+0])[lr] = pack2(av.x, av.x);
            ((ull*)AsD[q][lc+1])[lr] = pack2(av.y, av.y);
            ((ull*)AsD[q][lc+2])[lr] = pack2(av.z, av.z);
            ((ull*)AsD[q][lc+3])[lr] = pack2(av.w, av.w);
            if (doB) {
                Bs[q][lc+0][lrB] = wv.x;
                Bs[q][lc+1][lrB] = wv.y;
                Bs[q][lc+2][lrB] = wv.z;
                Bs[q][lc+3][lrB] = wv.w;
            }
        }
        __syncthreads();
    }

    #pragma unroll
    for (int i = 0; i < 8; i++) {
        int m   = m0 + ty*8 + i;
        int bb_ = m / L;
        int l   = m - bb_ * L;
        #pragma unroll
        for (int j = 0; j < 2; j++) {
            float lo, hi;
            unpack2(acc2[i][j], lo, hi);
            int n0j = n0 + tx*4 + 2*j;
            float v0 = lo + bias[n0j];
            float v1 = hi + bias[n0j + 1];
            if (head_major) {
                int hh0 = n0j >> 6, dk0 = n0j & 63;
                int hh1 = (n0j+1) >> 6, dk1 = (n0j+1) & 63;
                C[((size_t)(bb_*H_ + hh0) * L + l) * DK_ + dk0] = v0;
                C[((size_t)(bb_*H_ + hh1) * L + l) * DK_ + dk1] = v1;
            } else {
                C[(size_t)m * DM_ + n0j]     = v0;
                C[(size_t)m * DM_ + n0j + 1] = v1;
            }
        }
    }
}

// Merged Q/K/V projection: grid (64 + 256 + 256, 8), 256 threads.
__global__ void __launch_bounds__(256, 2)
qkv_gemm_kernel(const float* __restrict__ q_in, const float* __restrict__ k_in,
                const float* __restrict__ v_in,
                const float* __restrict__ Wq, const float* __restrict__ bq,
                const float* __restrict__ Wk, const float* __restrict__ bk,
                const float* __restrict__ Wv, const float* __restrict__ bv,
                float* __restrict__ pq, float* __restrict__ pk, float* __restrict__ pv)
{
    const int bx = blockIdx.x;
    const float *A, *W, *bias; float* C; int L, mblk;
    if (bx < 64)        { A = q_in; W = Wq; bias = bq; C = pq; L = LQ_; mblk = bx; }
    else if (bx < 320)  { A = k_in; W = Wk; bias = bk; C = pk; L = LM_; mblk = bx - 64; }
    else                { A = v_in; W = Wv; bias = bv; C = pv; L = LM_; mblk = bx - 320; }
    gemm_body(A, W, bias, C, L, 1, mblk * 128, blockIdx.y * 64);
}

// Output projection: plain row-major, grid (64, 8), 256 threads.
__global__ void __launch_bounds__(256, 2)
out_gemm_kernel(const float* __restrict__ A, const float* __restrict__ W,
                const float* __restrict__ bias, float* __restrict__ C)
{
    gemm_body(A, W, bias, C, LQ_, 0, blockIdx.x * 128, blockIdx.y * 64);
}

// ---------------------------------------------------------------------------
// Fused scores + EXACT top-32 (running register top-k, uint4 skip fast path)
// + softmax + V gather. VERBATIM round-8 version (bit-identical selection).
// One block per (b, h, 32-query tile); 256 threads; warp w owns rows 4w..4w+3.
// ---------------------------------------------------------------------------
__global__ void __launch_bounds__(256, 3)
attn_topk_kernel(const float* __restrict__ gq, const float* __restrict__ gk,
                 const float* __restrict__ gv, float* __restrict__ gx)
{
    extern __shared__ float sm[];
    float*    qs  = sm + OFF_QS;
    float*    ks  = sm + OFF_KS;                 // xor-swizzled float4 tile
    unsigned* scC = (unsigned*)(sm + OFF_SCC);   // QT x CK ordu scores

    const int t    = threadIdx.x;
    const int lane = t & 31;
    const int w    = t >> 5;               // warp id; owns rows 4w..4w+3
    const int qt0  = blockIdx.x * QT;
    const int h    = blockIdx.y;
    const int b    = blockIdx.z;
    const unsigned FULL = 0xffffffffu;

    // score-phase ownership: keys {kk, kk+64}, queries qh..qh+7
    const int kk = t & 63;
    const int qh = (t >> 6) << 3;

    // ---- load Q tile (32x64 fp32) ----
    const float* qbase = gq + ((size_t)(b*H_ + h) * LQ_ + qt0) * DK_;
    #pragma unroll
    for (int i = t; i < QT*DK_/4; i += 256)
        ((float4*)qs)[i] = ((const float4*)qbase)[i];

    const float* kbase = gk + (size_t)(b*H_ + h) * LM_ * DK_;

    // running top-32 state for the four rows owned by this warp
    unsigned bval[4] = {0u, 0u, 0u, 0u};
    int      bidx[4] = {0, 0, 0, 0};
    unsigned m[4]    = {0u, 0u, 0u, 0u};

    #pragma unroll 1
    for (int c0 = 0; c0 < LM_; c0 += CK) {
        __syncthreads();  // prev chunk's select done before scC/ks overwrite

        // ---- stage K chunk (CK x 64) with XOR swizzle: conflict-free ----
        #pragma unroll
        for (int i = t; i < CK*16; i += 256) {
            int row = i >> 4, col = i & 15;
            float4 v4 = ((const float4*)(kbase + (size_t)(c0 + row) * DK_))[col];
            ((float4*)ks)[(row << 4) | (col ^ (row & 15))] = v4;
        }
        __syncthreads();

        // ---- scores: thread owns keys kk, kk+64 and queries qh..qh+7;
        //      per-(q,k) FMA statement identical to rounds 4-8 ----
        {
            float acc0[8], acc1[8];
            #pragma unroll
            for (int qi = 0; qi < 8; qi++) { acc0[qi] = 0.f; acc1[qi] = 0.f; }
            const float4* ks4 = (const float4*)ks;
            const int kk2 = kk + 64;
            #pragma unroll
            for (int d4 = 0; d4 < DK_/4; d4++) {
                float4 kv0 = ks4[(kk  << 4) | (d4 ^ (kk  & 15))];
                float4 kv1 = ks4[(kk2 << 4) | (d4 ^ (kk2 & 15))];
                #pragma unroll
                for (int qi = 0; qi < 8; qi++) {
                    float4 qv = ((const float4*)(qs + (qh + qi)*DK_))[d4];
                    acc0[qi] += kv0.x*qv.x + kv0.y*qv.y + kv0.z*qv.z + kv0.w*qv.w;
                    acc1[qi] += kv1.x*qv.x + kv1.y*qv.y + kv1.z*qv.z + kv1.w*qv.w;
                }
            }
            #pragma unroll
            for (int qi = 0; qi < 8; qi++) {
                scC[(qh + qi)*CK + kk ] = ordu(acc0[qi] * 0.125f);  // 1/sqrt(64)
                scC[(qh + qi)*CK + kk2] = ordu(acc1[qi] * 0.125f);
            }
        }
        __syncthreads();

        // ---- select: warp w updates running top-32 for rows 4w..4w+3 ----
        #pragma unroll 1
        for (int rr = 0; rr < 4; rr++) {
            const int rowi = 4*w + rr;
            const unsigned* srow = scC + rowi*CK;

            bool slow;
            if (c0 == 0) {
                slow = true;   // includes initial fill
            } else {
                // fast path: one uint4 per lane covers the 128-key chunk.
                // Skipping when nothing exceeds m is exactly equivalent to
                // sequential processing (m is monotone non-decreasing).
                uint4 uu = ((const uint4*)srow)[lane];
                bool any = (uu.x > m[rr]) | (uu.y > m[rr]) |
                           (uu.z > m[rr]) | (uu.w > m[rr]);
                slow = (__ballot_sync(FULL, any) != 0u);
            }

            if (slow) {
                #pragma unroll 1
                for (int bb = 0; bb < CK/32; bb++) {
                    const int i0 = c0 + bb*32;
                    unsigned u = srow[bb*32 + lane];

                    if (c0 == 0 && bb == 0) {       // initial fill
                        bval[rr] = u; bidx[rr] = lane;
                        m[rr] = __reduce_min_sync(FULL, bval[rr]);
                        continue;
                    }

                    unsigned hit = __ballot_sync(FULL, u > m[rr]);
                    while (hit) {                    // warp-uniform rare path
                        int s = __ffs(hit) - 1; hit &= hit - 1;
                        unsigned uc = __shfl_sync(FULL, u, s);
                        if (uc > m[rr]) {            // recheck vs updated m
                            int ic = i0 + s;
                            unsigned em = __ballot_sync(FULL, bval[rr] == m[rr]);
                            int el;
                            if (__popc(em) > 1) {
                                // tie on min: evict LARGER index (jax keeps lower)
                                int cb = ((em >> lane) & 1) ? bidx[rr] : -1;
                                int mx = __reduce_max_sync(FULL, cb);
                                el = __ffs(__ballot_sync(FULL,
                                        (bval[rr] == m[rr]) && (bidx[rr] == mx))) - 1;
                            } else {
                                el = __ffs(em) - 1;
                            }
                            if (lane == el) { bval[rr] = uc; bidx[rr] = ic; }
                            m[rr] = __reduce_min_sync(FULL, bval[rr]);
                        }
                    }
                }
            }
        }
    }

    // ---- softmax + weighted V gather for the four rows ----
    const float* vbase = gv + (size_t)(b*H_ + h) * LM_ * DK_;
    #pragma unroll 1
    for (int rr = 0; rr < 4; rr++) {
        float v  = iordu(bval[rr]);
        float mx = v;
        #pragma unroll
        for (int off = 16; off; off >>= 1)
            mx = fmaxf(mx, __shfl_xor_sync(FULL, mx, off));
        float e = __expf(v - mx);
        float s = e;
        #pragma unroll
        for (int off = 16; off; off >>= 1)
            s += __shfl_xor_sync(FULL, s, off);
        float wgt = e / s;

        float a0 = 0.f, a1 = 0.f;
        #pragma unroll 4
        for (int it = 0; it < TOPK_; it++) {
            float wi = __shfl_sync(FULL, wgt, it);
            int   ki = __shfl_sync(FULL, bidx[rr], it);
            const float* vr = vbase + (size_t)ki * DK_;
            a0 = fmaf(wi, vr[lane],      a0);
            a1 = fmaf(wi, vr[lane + 32], a1);
        }
        float* orow = gx + ((size_t)b * LQ_ + (qt0 + 4*w + rr)) * DM_ + h*DK_;
        orow[lane]      = a0;
        orow[lane + 32] = a1;
    }
}

// ---------------------------------------------------------------------------
extern "C" void kernel_launch(void* const* d_in, const int* in_sizes, int n_in,
                              void* d_out, int out_size)
{
    const float* query = (const float*)d_in[0];
    const float* key   = (const float*)d_in[1];
    const float* value = (const float*)d_in[2];
    const float* Wq    = (const float*)d_in[3];
    const float* bq    = (const float*)d_in[4];
    const float* Wk    = (const float*)d_in[5];
    const float* bk    = (const float*)d_in[6];
    const float* Wv    = (const float*)d_in[7];
    const float* bv    = (const float*)d_in[8];
    const float* Wo    = (const float*)d_in[9];
    const float* bo    = (const float*)d_in[10];
    float* out = (float*)d_out;

    float *pq, *pk, *pv, *px;
    cudaGetSymbolAddress((void**)&pq, g_q);
    cudaGetSymbolAddress((void**)&pk, g_k);
    cudaGetSymbolAddress((void**)&pv, g_v);
    cudaGetSymbolAddress((void**)&px, g_x);

    cudaFuncSetAttribute(attn_topk_kernel,
                         cudaFuncAttributeMaxDynamicSharedMemorySize, SMEM_BYTES);

    // merged Q/K/V projections into head-major scratch (128x64 tiles)
    qkv_gemm_kernel<<<dim3(576, DM_/64), 256>>>(query, key, value,
                                                Wq, bq, Wk, bk, Wv, bv,
                                                pq, pk, pv);

    // fused scores + topk + softmax + gather
    attn_topk_kernel<<<dim3(LQ_/QT, H_, B_), 256, SMEM_BYTES>>>(pq, pk, pv, px);

    // output projection (plain row-major)
    out_gemm_kernel<<<dim3(B_*LQ_/128, DM_/64), 256>>>(px, Wo, bo, out);
}

// round 11
// speedup vs baseline: 1.6851x; 1.6851x over previous
#include <cuda_runtime.h>
#include <cstdint>

// Problem constants
constexpr int B_   = 8;
constexpr int H_   = 8;
constexpr int LQ_  = 1024;
constexpr int LM_  = 4096;
constexpr int DM_  = 512;
constexpr int DK_  = 64;
constexpr int TOPK_ = 32;

// Attention kernel tiling
constexpr int QT   = 32;    // queries per block (4 rows per warp)
constexpr int CK   = 128;   // key chunk cached in smem (32 KB)

// Scratch (static device arrays: allocation-free)
__device__ float g_q[B_*H_*LQ_*DK_];   // 16 MB  [B,H,LQ,Dk]
__device__ float g_k[B_*H_*LM_*DK_];   // 64 MB  [B,H,LM,Dk]
__device__ float g_v[B_*H_*LM_*DK_];   // 64 MB  [B,H,LM,Dk]
__device__ float g_x[B_*LQ_*DM_];      // 16 MB  [B,LQ,DM] pre-output-proj

// ---------------- attention smem layout (floats) ---------------------------
constexpr int OFF_QS  = 0;                 // 2048 : Q tile 32x64
constexpr int OFF_KS  = OFF_QS + QT*DK_;   // 8192 : K chunk 128x64, xor-swizzled float4
constexpr int OFF_SCC = OFF_KS + CK*DK_;   // 4096 : score staging 32x128 (ordu uints)
constexpr int SMEM_FLOATS = OFF_SCC + QT*CK;
constexpr int SMEM_BYTES  = SMEM_FLOATS * 4;   // 57344 B -> 3 blocks/SM

// order-preserving float -> uint, and inverse
__device__ __forceinline__ unsigned ordu(float x) {
    unsigned u = __float_as_uint(x);
    return (u & 0x80000000u) ? ~u : (u | 0x80000000u);
}
__device__ __forceinline__ float iordu(unsigned v) {
    unsigned u = (v & 0x80000000u) ? (v ^ 0x80000000u) : ~v;
    return __uint_as_float(u);
}

// ---------------- packed f32x2 primitives (lanewise IEEE fp32) -------------
typedef unsigned long long ull;

__device__ __forceinline__ ull pack2(float lo, float hi) {
    ull d; asm("mov.b64 %0, {%1, %2};" : "=l"(d) : "f"(lo), "f"(hi)); return d;
}
__device__ __forceinline__ void unpack2(ull v, float& lo, float& hi) {
    asm("mov.b64 {%0, %1}, %2;" : "=f"(lo), "=f"(hi) : "l"(v));
}
__device__ __forceinline__ ull fma2(ull a, ull b, ull c) {
    ull d; asm("fma.rn.f32x2 %0, %1, %2, %3;" : "=l"(d) : "l"(a), "l"(b), "l"(c)); return d;
}
__device__ __forceinline__ ull mul2(ull a, ull b) {
    ull d; asm("mul.rn.f32x2 %0, %1, %2;" : "=l"(d) : "l"(a), "l"(b)); return d;
}
__device__ __forceinline__ ull add2(ull a, ull b) {
    ull d; asm("add.rn.f32x2 %0, %1, %2;" : "=l"(d) : "l"(a), "l"(b)); return d;
}

// B smem row layout: per-tx pad to 10 floats -> 16 distinct banks for the
// 16 tx groups (10*tx mod 32 all distinct), 8B-aligned pairs for LDS.64.
constexpr int BROW = 160;   // 16 tx-groups * 10 floats
__device__ __forceinline__ int bswz(int n) { return (n >> 3) * 10 + (n & 7); }

// ---------------------------------------------------------------------------
// Shared SGEMM body (VERBATIM round-8 best): C = A[M,512] @ W[512,512]^T + bias.
// f32x2 packed FMA inner loop; per-element arithmetic (values and order)
// IDENTICAL to the scalar two-level version of rounds 2-7.
// 256 threads, 8x8 per thread, 128x128 tile at (m0, n0).
// ---------------------------------------------------------------------------
__device__ __forceinline__ void gemm_body(
    const float* __restrict__ A, const float* __restrict__ W,
    const float* __restrict__ bias, float* __restrict__ C,
    int L, int head_major, int m0, int n0)
{
    __shared__ __align__(16) float AsD[2][8][256];   // duplicated A: 16 KB
    __shared__ __align__(16) float Bs [2][8][BROW];  // padded B: 10 KB

    const int t  = threadIdx.x;
    const int tx = t & 15;
    const int ty = t >> 4;
    const int lr = t >> 1;
    const int lc = (t & 1) << 2;

    const float* Ap = A + (size_t)(m0 + lr) * DM_ + lc;
    const float* Wp = W + (size_t)(n0 + lr) * DM_ + lc;
    const int bofs = bswz(lr);

    // prologue: stage k-tile 0 into buffer 0
    {
        float4 av = *(const float4*)(Ap);
        float4 wv = *(const float4*)(Wp);
        ((ull*)AsD[0][lc+0])[lr] = pack2(av.x, av.x);
        ((ull*)AsD[0][lc+1])[lr] = pack2(av.y, av.y);
        ((ull*)AsD[0][lc+2])[lr] = pack2(av.z, av.z);
        ((ull*)AsD[0][lc+3])[lr] = pack2(av.w, av.w);
        Bs[0][lc+0][bofs] = wv.x;
        Bs[0][lc+1][bofs] = wv.y;
        Bs[0][lc+2][bofs] = wv.z;
        Bs[0][lc+3][bofs] = wv.w;
    }
    __syncthreads();

    ull acc2[8][4];
    #pragma unroll
    for (int i = 0; i < 8; i++)
        #pragma unroll
        for (int j = 0; j < 4; j++) acc2[i][j] = pack2(0.f, 0.f);

    #pragma unroll 1
    for (int k0 = 0; k0 < DM_; k0 += 8) {
        const int  p    = (k0 >> 3) & 1;
        const bool more = (k0 + 8) < DM_;
        float4 av, wv;
        if (more) {
            av = *(const float4*)(Ap + k0 + 8);
            wv = *(const float4*)(Wp + k0 + 8);
        }

        ull cacc2[8][4];
        #pragma unroll
        for (int k = 0; k < 8; k++) {
            // a (duplicated) : 8 ull = 4x LDS.128 broadcast
            ull a2[8];
            {
                const ulonglong2* ar = (const ulonglong2*)&AsD[p][k][0];
                #pragma unroll
                for (int ii = 0; ii < 4; ii++) {
                    ulonglong2 v = ar[ty*4 + ii];
                    a2[2*ii]   = v.x;
                    a2[2*ii+1] = v.y;
                }
            }
            // b pairs: 4x LDS.64, conflict-free via 10-float padding
            ull b2[4];
            {
                const ull* br = (const ull*)&Bs[p][k][tx*10];
                #pragma unroll
                for (int j = 0; j < 4; j++) b2[j] = br[j];
            }
            if (k == 0) {
                #pragma unroll
                for (int i = 0; i < 8; i++)
                    #pragma unroll
                    for (int j = 0; j < 4; j++)
                        cacc2[i][j] = mul2(a2[i], b2[j]);
            } else {
                #pragma unroll
                for (int i = 0; i < 8; i++)
                    #pragma unroll
                    for (int j = 0; j < 4; j++)
                        cacc2[i][j] = fma2(a2[i], b2[j], cacc2[i][j]);
            }
        }
        #pragma unroll
        for (int i = 0; i < 8; i++)
            #pragma unroll
            for (int j = 0; j < 4; j++)
                acc2[i][j] = add2(acc2[i][j], cacc2[i][j]);

        if (more) {
            const int q = p ^ 1;
            ((ull*)AsD[q][lc+0])[lr] = pack2(av.x, av.x);
            ((ull*)AsD[q][lc+1])[lr] = pack2(av.y, av.y);
            ((ull*)AsD[q][lc+2])[lr] = pack2(av.z, av.z);
            ((ull*)AsD[q][lc+3])[lr] = pack2(av.w, av.w);
            Bs[q][lc+0][bofs] = wv.x;
            Bs[q][lc+1][bofs] = wv.y;
            Bs[q][lc+2][bofs] = wv.z;
            Bs[q][lc+3][bofs] = wv.w;
        }
        __syncthreads();
    }

    #pragma unroll
    for (int i = 0; i < 8; i++) {
        int m  = m0 + ty*8 + i;
        int bb_ = m / L;
        int l   = m - bb_ * L;
        #pragma unroll
        for (int j = 0; j < 4; j++) {
            float lo, hi;
            unpack2(acc2[i][j], lo, hi);
            int n0j = n0 + tx*8 + 2*j;
            float v0 = lo + bias[n0j];
            float v1 = hi + bias[n0j + 1];
            if (head_major) {
                int hh0 = n0j >> 6, dk0 = n0j & 63;
                int hh1 = (n0j+1) >> 6, dk1 = (n0j+1) & 63;
                C[((size_t)(bb_*H_ + hh0) * L + l) * DK_ + dk0] = v0;
                C[((size_t)(bb_*H_ + hh1) * L + l) * DK_ + dk1] = v1;
            } else {
                C[(size_t)m * DM_ + n0j]     = v0;
                C[(size_t)m * DM_ + n0j + 1] = v1;
            }
        }
    }
}

// Merged Q/K/V projection: grid (64 + 256 + 256, 4).
__global__ void __launch_bounds__(256, 1)
qkv_gemm_kernel(const float* __restrict__ q_in, const float* __restrict__ k_in,
                const float* __restrict__ v_in,
                const float* __restrict__ Wq, const float* __restrict__ bq,
                const float* __restrict__ Wk, const float* __restrict__ bk,
                const float* __restrict__ Wv, const float* __restrict__ bv,
                float* __restrict__ pq, float* __restrict__ pk, float* __restrict__ pv)
{
    const int bx = blockIdx.x;
    const float *A, *W, *bias; float* C; int L, mblk;
    if (bx < 64)        { A = q_in; W = Wq; bias = bq; C = pq; L = LQ_; mblk = bx; }
    else if (bx < 320)  { A = k_in; W = Wk; bias = bk; C = pk; L = LM_; mblk = bx - 64; }
    else                { A = v_in; W = Wv; bias = bv; C = pv; L = LM_; mblk = bx - 320; }
    gemm_body(A, W, bias, C, L, 1, mblk * 128, blockIdx.y * 128);
}

// Output projection: plain row-major.
__global__ void __launch_bounds__(256, 1)
out_gemm_kernel(const float* __restrict__ A, const float* __restrict__ W,
                const float* __restrict__ bias, float* __restrict__ C)
{
    gemm_body(A, W, bias, C, LQ_, 0, blockIdx.x * 128, blockIdx.y * 128);
}

// ---------------------------------------------------------------------------
// Fused scores + EXACT top-32 + softmax + V gather — round-8 arithmetic and
// selection order, SOFTWARE-PIPELINED: select(c-1) overlaps stage(c)'s LDG,
// and one barrier per chunk is removed (3 -> 2 syncs/chunk).
//   stage(0); sync; scores(0); sync;
//   loop c: stage(c); select(c-1); sync; scores(c); sync;
//   select(last)
// Safety: select(c-1) reads scC strictly before the sync preceding scores(c)'s
// scC overwrite; stage(c) writes only ks, which all warps finished reading
// (scores(c-1)) before the previous sync. Selection visits batches in the same
// ascending key order => bit-identical selection.
// ---------------------------------------------------------------------------
__global__ void __launch_bounds__(256, 3)
attn_topk_kernel(const float* __restrict__ gq, const float* __restrict__ gk,
                 const float* __restrict__ gv, float* __restrict__ gx)
{
    extern __shared__ float sm[];
    float*    qs  = sm + OFF_QS;
    float*    ks  = sm + OFF_KS;                 // xor-swizzled float4 tile
    unsigned* scC = (unsigned*)(sm + OFF_SCC);   // QT x CK ordu scores

    const int t    = threadIdx.x;
    const int lane = t & 31;
    const int w    = t >> 5;               // warp id; owns rows 4w..4w+3
    const int qt0  = blockIdx.x * QT;
    const int h    = blockIdx.y;
    const int b    = blockIdx.z;
    const unsigned FULL = 0xffffffffu;

    // score-phase ownership: keys {kk, kk+64}, queries qh..qh+7
    const int kk = t & 63;
    const int qh = (t >> 6) << 3;

    // ---- load Q tile (32x64 fp32) ----
    const float* qbase = gq + ((size_t)(b*H_ + h) * LQ_ + qt0) * DK_;
    #pragma unroll
    for (int i = t; i < QT*DK_/4; i += 256)
        ((float4*)qs)[i] = ((const float4*)qbase)[i];

    const float* kbase = gk + (size_t)(b*H_ + h) * LM_ * DK_;

    // running top-32 state for the four rows owned by this warp
    unsigned bval[4] = {0u, 0u, 0u, 0u};
    int      bidx[4] = {0, 0, 0, 0};
    unsigned m[4]    = {0u, 0u, 0u, 0u};

    // ---- stage K chunk (CK x 64) with XOR swizzle: conflict-free ----
    auto stage = [&](int c0) {
        #pragma unroll
        for (int i = t; i < CK*16; i += 256) {
            int row = i >> 4, col = i & 15;
            float4 v4 = ((const float4*)(kbase + (size_t)(c0 + row) * DK_))[col];
            ((float4*)ks)[(row << 4) | (col ^ (row & 15))] = v4;
        }
    };

    // ---- scores: thread owns keys kk, kk+64 and queries qh..qh+7;
    //      per-(q,k) FMA statement identical to rounds 4-8 ----
    auto do_scores = [&]() {
        float acc0[8], acc1[8];
        #pragma unroll
        for (int qi = 0; qi < 8; qi++) { acc0[qi] = 0.f; acc1[qi] = 0.f; }
        const float4* ks4 = (const float4*)ks;
        const int kk2 = kk + 64;
        #pragma unroll
        for (int d4 = 0; d4 < DK_/4; d4++) {
            float4 kv0 = ks4[(kk  << 4) | (d4 ^ (kk  & 15))];
            float4 kv1 = ks4[(kk2 << 4) | (d4 ^ (kk2 & 15))];
            #pragma unroll
            for (int qi = 0; qi < 8; qi++) {
                float4 qv = ((const float4*)(qs + (qh + qi)*DK_))[d4];
                acc0[qi] += kv0.x*qv.x + kv0.y*qv.y + kv0.z*qv.z + kv0.w*qv.w;
                acc1[qi] += kv1.x*qv.x + kv1.y*qv.y + kv1.z*qv.z + kv1.w*qv.w;
            }
        }
        #pragma unroll
        for (int qi = 0; qi < 8; qi++) {
            scC[(qh + qi)*CK + kk ] = ordu(acc0[qi] * 0.125f);  // 1/sqrt(64)
            scC[(qh + qi)*CK + kk2] = ordu(acc1[qi] * 0.125f);
        }
    };

    // ---- select: warp w updates running top-32 for rows 4w..4w+3 from the
    //      scC scores of the chunk that starts at key index 'base' ----
    auto select_chunk = [&](int base) {
        #pragma unroll 1
        for (int rr = 0; rr < 4; rr++) {
            const int rowi = 4*w + rr;
            const unsigned* srow = scC + rowi*CK;

            bool slow;
            if (base == 0) {
                slow = true;   // includes initial fill
            } else {
                // fast path: one uint4 per lane covers the 128-key chunk.
                // Skipping when nothing exceeds m is exactly equivalent to
                // sequential processing (m is monotone non-decreasing).
                uint4 uu = ((const uint4*)srow)[lane];
                bool any = (uu.x > m[rr]) | (uu.y > m[rr]) |
                           (uu.z > m[rr]) | (uu.w > m[rr]);
                slow = (__ballot_sync(FULL, any) != 0u);
            }

            if (slow) {
                #pragma unroll 1
                for (int bb = 0; bb < CK/32; bb++) {
                    const int i0 = base + bb*32;
                    unsigned u = srow[bb*32 + lane];

                    if (base == 0 && bb == 0) {     // initial fill
                        bval[rr] = u; bidx[rr] = lane;
                        m[rr] = __reduce_min_sync(FULL, bval[rr]);
                        continue;
                    }

                    unsigned hit = __ballot_sync(FULL, u > m[rr]);
                    while (hit) {                    // warp-uniform rare path
                        int s = __ffs(hit) - 1; hit &= hit - 1;
                        unsigned uc = __shfl_sync(FULL, u, s);
                        if (uc > m[rr]) {            // recheck vs updated m
                            int ic = i0 + s;
                            unsigned em = __ballot_sync(FULL, bval[rr] == m[rr]);
                            int el;
                            if (__popc(em) > 1) {
                                // tie on min: evict LARGER index (jax keeps lower)
                                int cb = ((em >> lane) & 1) ? bidx[rr] : -1;
                                int mx = __reduce_max_sync(FULL, cb);
                                el = __ffs(__ballot_sync(FULL,
                                        (bval[rr] == m[rr]) && (bidx[rr] == mx))) - 1;
                            } else {
                                el = __ffs(em) - 1;
                            }
                            if (lane == el) { bval[rr] = uc; bidx[rr] = ic; }
                            m[rr] = __reduce_min_sync(FULL, bval[rr]);
                        }
                    }
                }
            }
        }
    };

    // ---- software-pipelined main loop ----
    stage(0);
    __syncthreads();
    do_scores();
    __syncthreads();

    #pragma unroll 1
    for (int c0 = CK; c0 < LM_; c0 += CK) {
        stage(c0);                 // LDG in flight while select runs
        select_chunk(c0 - CK);     // reads scC of previous chunk
        __syncthreads();
        do_scores();               // overwrites scC (guarded by sync)
        __syncthreads();
    }
    select_chunk(LM_ - CK);

    // ---- softmax + weighted V gather for the four rows ----
    const float* vbase = gv + (size_t)(b*H_ + h) * LM_ * DK_;
    #pragma unroll 1
    for (int rr = 0; rr < 4; rr++) {
        float v  = iordu(bval[rr]);
        float mx = v;
        #pragma unroll
        for (int off = 16; off; off >>= 1)
            mx = fmaxf(mx, __shfl_xor_sync(FULL, mx, off));
        float e = __expf(v - mx);
        float s = e;
        #pragma unroll
        for (int off = 16; off; off >>= 1)
            s += __shfl_xor_sync(FULL, s, off);
        float wgt = e / s;

        float a0 = 0.f, a1 = 0.f;
        #pragma unroll 4
        for (int it = 0; it < TOPK_; it++) {
            float wi = __shfl_sync(FULL, wgt, it);
            int   ki = __shfl_sync(FULL, bidx[rr], it);
            const float* vr = vbase + (size_t)ki * DK_;
            a0 = fmaf(wi, vr[lane],      a0);
            a1 = fmaf(wi, vr[lane + 32], a1);
        }
        float* orow = gx + ((size_t)b * LQ_ + (qt0 + 4*w + rr)) * DM_ + h*DK_;
        orow[lane]      = a0;
        orow[lane + 32] = a1;
    }
}

// ---------------------------------------------------------------------------
extern "C" void kernel_launch(void* const* d_in, const int* in_sizes, int n_in,
                              void* d_out, int out_size)
{
    const float* query = (const float*)d_in[0];
    const float* key   = (const float*)d_in[1];
    const float* value = (const float*)d_in[2];
    const float* Wq    = (const float*)d_in[3];
    const float* bq    = (const float*)d_in[4];
    const float* Wk    = (const float*)d_in[5];
    const float* bk    = (const float*)d_in[6];
    const float* Wv    = (const float*)d_in[7];
    const float* bv    = (const float*)d_in[8];
    const float* Wo    = (const float*)d_in[9];
    const float* bo    = (const float*)d_in[10];
    float* out = (float*)d_out;

    float *pq, *pk, *pv, *px;
    cudaGetSymbolAddress((void**)&pq, g_q);
    cudaGetSymbolAddress((void**)&pk, g_k);
    cudaGetSymbolAddress((void**)&pv, g_v);
    cudaGetSymbolAddress((void**)&px, g_x);

    cudaFuncSetAttribute(attn_topk_kernel,
                         cudaFuncAttributeMaxDynamicSharedMemorySize, SMEM_BYTES);

    // merged Q/K/V projections into head-major scratch (round-8 geometry)
    qkv_gemm_kernel<<<dim3(576, DM_/128), 256>>>(query, key, value,
                                                 Wq, bq, Wk, bk, Wv, bv,
                                                 pq, pk, pv);

    // fused scores + topk + softmax + gather
    attn_topk_kernel<<<dim3(LQ_/QT, H_, B_), 256, SMEM_BYTES>>>(pq, pk, pv, px);

    // output projection (plain row-major)
    out_gemm_kernel<<<dim3(B_*LQ_/128, DM_/128), 256>>>(px, Wo, bo, out);
}